// round 2
// baseline (speedup 1.0000x reference)
#include <cuda_runtime.h>
#include <math.h>

#define SEQ  2048
#define EMB  2048
#define NH   16
#define HD   128

// ---------------- scratch (allocation-free: static device globals, 64 MB) --------
__device__ float g_q[(size_t)SEQ * EMB];
__device__ float g_k[(size_t)SEQ * EMB];
__device__ float g_v[(size_t)SEQ * EMB];
__device__ float g_ctx[(size_t)SEQ * EMB];

// ---------------- tiled NT GEMM: C = A @ B^T  (A:[M,K], B:[N,K]) ----------------
#define BM 64
#define BN 64
#define BK 16

__global__ void __launch_bounds__(256) gemm_nt(
    const float* __restrict__ A, const float* __restrict__ B, float* __restrict__ C,
    int M, int N, int K, int lda, int ldb, int ldc)
{
    __shared__ float As[BK][BM + 4];
    __shared__ float Bs[BK][BN + 4];

    const int t  = threadIdx.x;
    const int tx = t & 15;
    const int ty = t >> 4;
    const int m0 = blockIdx.y * BM;
    const int n0 = blockIdx.x * BN;

    const int ar = t >> 2;          // 0..63 row within tile
    const int ac = (t & 3) * 4;     // 0,4,8,12 col within tile

    float acc[4][4];
#pragma unroll
    for (int i = 0; i < 4; i++)
#pragma unroll
        for (int j = 0; j < 4; j++) acc[i][j] = 0.0f;

    for (int k0 = 0; k0 < K; k0 += BK) {
        float4 av = *(const float4*)(A + (size_t)(m0 + ar) * lda + (k0 + ac));
        As[ac + 0][ar] = av.x;
        As[ac + 1][ar] = av.y;
        As[ac + 2][ar] = av.z;
        As[ac + 3][ar] = av.w;

        float4 bv = *(const float4*)(B + (size_t)(n0 + ar) * ldb + (k0 + ac));
        Bs[ac + 0][ar] = bv.x;
        Bs[ac + 1][ar] = bv.y;
        Bs[ac + 2][ar] = bv.z;
        Bs[ac + 3][ar] = bv.w;
        __syncthreads();

#pragma unroll
        for (int kk = 0; kk < BK; kk++) {
            float4 a4 = *(const float4*)&As[kk][ty * 4];
            float4 b4 = *(const float4*)&Bs[kk][tx * 4];
            float a[4] = {a4.x, a4.y, a4.z, a4.w};
            float b[4] = {b4.x, b4.y, b4.z, b4.w};
#pragma unroll
            for (int i = 0; i < 4; i++)
#pragma unroll
                for (int j = 0; j < 4; j++) acc[i][j] += a[i] * b[j];
        }
        __syncthreads();
    }

#pragma unroll
    for (int i = 0; i < 4; i++) {
        float4 o;
        o.x = acc[i][0]; o.y = acc[i][1]; o.z = acc[i][2]; o.w = acc[i][3];
        *(float4*)(C + (size_t)(m0 + ty * 4 + i) * ldc + (n0 + tx * 4)) = o;
    }
}

// ---------------- RoPE (in-place on Q and K, [S,E] layout) ----------------
__global__ void __launch_bounds__(64) rope_kernel(float* __restrict__ q, float* __restrict__ k)
{
    const int s = blockIdx.x;
    const int h = blockIdx.y;
    const int i = threadIdx.x;  // 0..63 pair index

    const float inv_freq = powf(10000.0f, -(float)i * (1.0f / 64.0f));
    const float ang = (float)s * inv_freq;
    const float c  = cosf(ang);
    const float sn = sinf(ang);

    const size_t base = (size_t)s * EMB + (size_t)h * HD;

    {
        float x0 = q[base + i], x1 = q[base + i + 64];
        q[base + i]      = x0 * c - x1 * sn;
        q[base + i + 64] = x1 * c + x0 * sn;
    }
    {
        float x0 = k[base + i], x1 = k[base + i + 64];
        k[base + i]      = x0 * c - x1 * sn;
        k[base + i + 64] = x1 * c + x0 * sn;
    }
}

// ---------------- fused flash attention: ctx = softmax(QK^T/sqrt(D)) @ V --------
// One CTA per (64 query rows, head). 256 threads. Online softmax, O in registers.
// Dynamic smem: Qt[128][68] + Kt[128][68] + Vs[64][132] + Ps[64][64]  = 119808 B
#define FQT_STRIDE 68
#define FV_STRIDE  132
#define FSMEM_FLOATS (128*FQT_STRIDE*2 + 64*FV_STRIDE + 64*64)
#define FSMEM_BYTES  (FSMEM_FLOATS * 4)

__global__ void __launch_bounds__(256) flash_kernel(
    const float* __restrict__ q, const float* __restrict__ k,
    const float* __restrict__ v, float* __restrict__ ctx)
{
    extern __shared__ float smem[];
    float* Qt = smem;                      // [128][68]  (k-major, transposed)
    float* Kt = Qt + 128 * FQT_STRIDE;     // [128][68]
    float* Vs = Kt + 128 * FQT_STRIDE;     // [64][132]
    float* Ps = Vs + 64 * FV_STRIDE;       // [64][64]

    const int t  = threadIdx.x;
    const int tx = t & 15;
    const int ty = t >> 4;
    const int h  = blockIdx.y;
    const int m0 = blockIdx.x * 64;
    const int hb = h * HD;
    const float SCALE = 0.08838834764831845f;   // 1/sqrt(128)

    // load Q block transposed: Qt[c][m]
    for (int i = t; i < 64 * 32; i += 256) {
        const int row = i >> 5;
        const int cg  = (i & 31) << 2;
        float4 x = *(const float4*)(q + (size_t)(m0 + row) * EMB + hb + cg);
        Qt[(cg + 0) * FQT_STRIDE + row] = x.x;
        Qt[(cg + 1) * FQT_STRIDE + row] = x.y;
        Qt[(cg + 2) * FQT_STRIDE + row] = x.z;
        Qt[(cg + 3) * FQT_STRIDE + row] = x.w;
    }

    float o[4][8];
    float mrow[4], lrow[4];
#pragma unroll
    for (int i = 0; i < 4; i++) {
        mrow[i] = -1.0e30f;
        lrow[i] = 0.0f;
#pragma unroll
        for (int d = 0; d < 8; d++) o[i][d] = 0.0f;
    }
    __syncthreads();

    for (int kb = 0; kb < SEQ / 64; kb++) {
        const int n0 = kb * 64;
        // load K block transposed + V block direct
        for (int i = t; i < 64 * 32; i += 256) {
            const int row = i >> 5;
            const int cg  = (i & 31) << 2;
            float4 x = *(const float4*)(k + (size_t)(n0 + row) * EMB + hb + cg);
            Kt[(cg + 0) * FQT_STRIDE + row] = x.x;
            Kt[(cg + 1) * FQT_STRIDE + row] = x.y;
            Kt[(cg + 2) * FQT_STRIDE + row] = x.z;
            Kt[(cg + 3) * FQT_STRIDE + row] = x.w;
            float4 y = *(const float4*)(v + (size_t)(n0 + row) * EMB + hb + cg);
            *(float4*)&Vs[row * FV_STRIDE + cg] = y;
        }
        __syncthreads();

        // S = Q @ K^T (64x64), each thread 4x4
        float s[4][4];
#pragma unroll
        for (int i = 0; i < 4; i++)
#pragma unroll
            for (int j = 0; j < 4; j++) s[i][j] = 0.0f;

#pragma unroll 4
        for (int c = 0; c < 128; c++) {
            float4 a4 = *(const float4*)&Qt[c * FQT_STRIDE + ty * 4];
            float4 b4 = *(const float4*)&Kt[c * FQT_STRIDE + tx * 4];
            float a[4] = {a4.x, a4.y, a4.z, a4.w};
            float b[4] = {b4.x, b4.y, b4.z, b4.w};
#pragma unroll
            for (int i = 0; i < 4; i++)
#pragma unroll
                for (int j = 0; j < 4; j++) s[i][j] += a[i] * b[j];
        }

        // online softmax update (rows spread over 16-lane subgroups: same ty)
#pragma unroll
        for (int i = 0; i < 4; i++) {
            float mloc = fmaxf(fmaxf(s[i][0] * SCALE, s[i][1] * SCALE),
                               fmaxf(s[i][2] * SCALE, s[i][3] * SCALE));
#pragma unroll
            for (int off = 1; off < 16; off <<= 1)
                mloc = fmaxf(mloc, __shfl_xor_sync(0xffffffffu, mloc, off));
            const float mnew = fmaxf(mrow[i], mloc);
            const float corr = __expf(mrow[i] - mnew);
            float p[4], psum = 0.0f;
#pragma unroll
            for (int j = 0; j < 4; j++) {
                p[j] = __expf(s[i][j] * SCALE - mnew);
                psum += p[j];
            }
#pragma unroll
            for (int off = 1; off < 16; off <<= 1)
                psum += __shfl_xor_sync(0xffffffffu, psum, off);
            lrow[i] = lrow[i] * corr + psum;
            mrow[i] = mnew;
#pragma unroll
            for (int d = 0; d < 8; d++) o[i][d] *= corr;
#pragma unroll
            for (int j = 0; j < 4; j++)
                Ps[(ty * 4 + i) * 64 + tx * 4 + j] = p[j];
        }
        __syncthreads();

        // O += P @ V  (64x128), each thread 4 rows x 8 cols (cols = tx*8..tx*8+7)
#pragma unroll 2
        for (int nn = 0; nn < 64; nn += 4) {
            float4 a[4];
#pragma unroll
            for (int i = 0; i < 4; i++)
                a[i] = *(const float4*)&Ps[(ty * 4 + i) * 64 + nn];
#pragma unroll
            for (int jj = 0; jj < 4; jj++) {
                float4 v0 = *(const float4*)&Vs[(nn + jj) * FV_STRIDE + tx * 8];
                float4 v1 = *(const float4*)&Vs[(nn + jj) * FV_STRIDE + tx * 8 + 4];
#pragma unroll
                for (int i = 0; i < 4; i++) {
                    const float av = (&a[i].x)[jj];
                    o[i][0] += av * v0.x; o[i][1] += av * v0.y;
                    o[i][2] += av * v0.z; o[i][3] += av * v0.w;
                    o[i][4] += av * v1.x; o[i][5] += av * v1.y;
                    o[i][6] += av * v1.z; o[i][7] += av * v1.w;
                }
            }
        }
        __syncthreads();
    }

    // write ctx[m][h*128 + d]
#pragma unroll
    for (int i = 0; i < 4; i++) {
        const float inv = 1.0f / lrow[i];
        float4 w0, w1;
        w0.x = o[i][0] * inv; w0.y = o[i][1] * inv; w0.z = o[i][2] * inv; w0.w = o[i][3] * inv;
        w1.x = o[i][4] * inv; w1.y = o[i][5] * inv; w1.z = o[i][6] * inv; w1.w = o[i][7] * inv;
        float* dst = ctx + (size_t)(m0 + ty * 4 + i) * EMB + hb + tx * 8;
        *(float4*)dst = w0;
        *(float4*)(dst + 4) = w1;
    }
}

// ---------------- launch ----------------
extern "C" void kernel_launch(void* const* d_in, const int* in_sizes, int n_in,
                              void* d_out, int out_size)
{
    const float* hs = (const float*)d_in[0];
    const float* Wq = (const float*)d_in[1];
    const float* Wk = (const float*)d_in[2];
    const float* Wv = (const float*)d_in[3];
    const float* Wo = (const float*)d_in[4];
    float* out = (float*)d_out;

    float *q, *k, *v, *ctx;
    cudaGetSymbolAddress((void**)&q,   g_q);
    cudaGetSymbolAddress((void**)&k,   g_k);
    cudaGetSymbolAddress((void**)&v,   g_v);
    cudaGetSymbolAddress((void**)&ctx, g_ctx);

    cudaFuncSetAttribute(flash_kernel, cudaFuncAttributeMaxDynamicSharedMemorySize, FSMEM_BYTES);

    const dim3 blk(256);
    const dim3 gFull(EMB / BN, SEQ / BM, 1);   // 32x32

    gemm_nt<<<gFull, blk>>>(hs, Wq, q, SEQ, EMB, EMB, EMB, EMB, EMB);
    gemm_nt<<<gFull, blk>>>(hs, Wk, k, SEQ, EMB, EMB, EMB, EMB, EMB);
    gemm_nt<<<gFull, blk>>>(hs, Wv, v, SEQ, EMB, EMB, EMB, EMB, EMB);

    rope_kernel<<<dim3(SEQ, NH), 64>>>(q, k);

    flash_kernel<<<dim3(SEQ / 64, NH), blk, FSMEM_BYTES>>>(q, k, v, ctx);

    gemm_nt<<<gFull, blk>>>(ctx, Wo, out, SEQ, EMB, EMB, EMB, EMB, EMB);
}

// round 6
// speedup vs baseline: 1.4753x; 1.4753x over previous
#include <cuda_runtime.h>
#include <cuda_bf16.h>
#include <cstdint>
#include <math.h>

#define SEQ  2048
#define EMB  2048
#define NH   16
#define HD   128

// ---------------- scratch (allocation-free: static device globals, 64 MB) --------
__device__ float g_q[(size_t)SEQ * EMB];
__device__ float g_k[(size_t)SEQ * EMB];
__device__ float g_v[(size_t)SEQ * EMB];
__device__ float g_ctx[(size_t)SEQ * EMB];

// ======================= warp-MMA helpers (sm_100 base target OK) ==============
__device__ __forceinline__ uint32_t smem_u32(const void* p) {
    uint32_t a;
    asm("{ .reg .u64 t; cvta.to.shared.u64 t, %1; cvt.u32.u64 %0, t; }" : "=r"(a) : "l"(p));
    return a;
}
#define LDSM4(r0, r1, r2, r3, addr)                                               \
    asm volatile("ldmatrix.sync.aligned.m8n8.x4.shared.b16 {%0,%1,%2,%3}, [%4];"  \
        : "=r"(r0), "=r"(r1), "=r"(r2), "=r"(r3) : "r"(addr))
#define MMA_BF16(c, a, b0, b1)                                                    \
    asm volatile("mma.sync.aligned.m16n8k16.row.col.f32.bf16.bf16.f32 "           \
        "{%0,%1,%2,%3}, {%4,%5,%6,%7}, {%8,%9}, {%0,%1,%2,%3};"                   \
        : "+f"((c)[0]), "+f"((c)[1]), "+f"((c)[2]), "+f"((c)[3])                  \
        : "r"((a)[0]), "r"((a)[1]), "r"((a)[2]), "r"((a)[3]), "r"(b0), "r"(b1))

// ============ HMMA NT GEMM: C[2048x2048] = A[M,K] @ B[N,K]^T (fp32 in/out) =====
// split-bf16 3-term: C = Ah*Bh + Ah*Bl + Al*Bh, fp32 accumulate in registers.
// CTA 128x128, 8 warps (4x2), warp tile 32x64, K chunk 32, double-buffered smem.
#define KC      32
#define NCHUNK  (EMB / KC)          // 64
#define RSTRIDE 40                  // bf16 elems per row (80B: conflict-free ldmatrix)
#define BUF_E   (128 * RSTRIDE)     // 5120 bf16 per matrix buffer
#define STAGE_E (4 * BUF_E)         // Ah, Al, Bh, Bl
#define GSM_BYTES (2 * STAGE_E * 2) // 81920

__global__ void __launch_bounds__(256) gemm_mma(
    const float* __restrict__ A,
    const float* __restrict__ B0, const float* __restrict__ B1, const float* __restrict__ B2,
    float* __restrict__ C0, float* __restrict__ C1, float* __restrict__ C2)
{
    const float* B = (blockIdx.z == 0) ? B0 : (blockIdx.z == 1) ? B1 : B2;
    float*       C = (blockIdx.z == 0) ? C0 : (blockIdx.z == 1) ? C1 : C2;

    extern __shared__ __align__(16) __nv_bfloat16 sm[];

    const int t    = threadIdx.x;
    const int lane = t & 31;
    const int wid  = t >> 5;
    const int wm   = wid & 3;          // 0..3  -> 32-row band
    const int wn   = wid >> 2;         // 0..1  -> 64-col band
    const int m0   = blockIdx.y * 128;
    const int n0   = blockIdx.x * 128;

    const int id = lane >> 3;          // ldmatrix matrix id
    const int r8 = lane & 7;

    float acc[2][8][4];
#pragma unroll
    for (int i = 0; i < 2; i++)
#pragma unroll
        for (int j = 0; j < 8; j++)
#pragma unroll
            for (int c = 0; c < 4; c++) acc[i][j][c] = 0.0f;

    float4 pref[8];

    // ---- loader: A/B chunk [128 rows x 32 cols] into registers ----
    auto LOADG = [&](int k0) {
#pragma unroll
        for (int j = 0; j < 4; j++) {
            const int idx = j * 256 + t;       // 0..1023
            const int row = idx >> 3;          // 0..127
            const int cg  = (idx & 7) << 2;    // 0..28
            pref[j]     = *(const float4*)(A + (size_t)(m0 + row) * EMB + k0 + cg);
            pref[4 + j] = *(const float4*)(B + (size_t)(n0 + row) * EMB + k0 + cg);
        }
    };
    // ---- split-convert + store into stage s ----
    auto STORES = [&](int s) {
        __nv_bfloat16* st = sm + s * STAGE_E;
#pragma unroll
        for (int mat = 0; mat < 2; mat++) {
            __nv_bfloat16* dh = st + (mat ? 2 * BUF_E : 0);
            __nv_bfloat16* dl = dh + BUF_E;
#pragma unroll
            for (int j = 0; j < 4; j++) {
                const int idx = j * 256 + t;
                const int row = idx >> 3;
                const int cg  = (idx & 7) << 2;
                float4 x = pref[mat * 4 + j];
                __nv_bfloat16 h0 = __float2bfloat16(x.x);
                __nv_bfloat16 h1 = __float2bfloat16(x.y);
                __nv_bfloat16 h2 = __float2bfloat16(x.z);
                __nv_bfloat16 h3 = __float2bfloat16(x.w);
                __nv_bfloat16 l0 = __float2bfloat16(x.x - __bfloat162float(h0));
                __nv_bfloat16 l1 = __float2bfloat16(x.y - __bfloat162float(h1));
                __nv_bfloat16 l2 = __float2bfloat16(x.z - __bfloat162float(h2));
                __nv_bfloat16 l3 = __float2bfloat16(x.w - __bfloat162float(h3));
                __nv_bfloat162 hp0 = __halves2bfloat162(h0, h1);
                __nv_bfloat162 hp1 = __halves2bfloat162(h2, h3);
                __nv_bfloat162 lp0 = __halves2bfloat162(l0, l1);
                __nv_bfloat162 lp1 = __halves2bfloat162(l2, l3);
                const int o = row * RSTRIDE + cg;
                *(uint2*)(dh + o) = make_uint2(*(uint32_t*)&hp0, *(uint32_t*)&hp1);
                *(uint2*)(dl + o) = make_uint2(*(uint32_t*)&lp0, *(uint32_t*)&lp1);
            }
        }
    };
    // ---- compute on stage s ----
    auto COMPUTE = [&](int s) {
        const uint32_t uAh = smem_u32(sm + s * STAGE_E);
        const uint32_t uAl = uAh + BUF_E * 2;
        const uint32_t uBh = uAl + BUF_E * 2;
        const uint32_t uBl = uBh + BUF_E * 2;
#pragma unroll
        for (int kk = 0; kk < KC; kk += 16) {
            uint32_t ah[2][4], al[2][4];
#pragma unroll
            for (int mt = 0; mt < 2; mt++) {
                const uint32_t offA =
                    ((wm * 32 + mt * 16 + (id & 1) * 8 + r8) * RSTRIDE + kk + (id >> 1) * 8) * 2;
                LDSM4(ah[mt][0], ah[mt][1], ah[mt][2], ah[mt][3], uAh + offA);
                LDSM4(al[mt][0], al[mt][1], al[mt][2], al[mt][3], uAl + offA);
            }
#pragma unroll
            for (int nt2 = 0; nt2 < 4; nt2++) {
                const uint32_t offB =
                    ((wn * 64 + nt2 * 16 + (id >> 1) * 8 + r8) * RSTRIDE + kk + (id & 1) * 8) * 2;
                uint32_t bh[4], bl[4];
                LDSM4(bh[0], bh[1], bh[2], bh[3], uBh + offB);
                LDSM4(bl[0], bl[1], bl[2], bl[3], uBl + offB);
#pragma unroll
                for (int mt = 0; mt < 2; mt++) {
                    MMA_BF16(acc[mt][nt2 * 2],     ah[mt], bh[0], bh[1]);
                    MMA_BF16(acc[mt][nt2 * 2],     ah[mt], bl[0], bl[1]);
                    MMA_BF16(acc[mt][nt2 * 2],     al[mt], bh[0], bh[1]);
                    MMA_BF16(acc[mt][nt2 * 2 + 1], ah[mt], bh[2], bh[3]);
                    MMA_BF16(acc[mt][nt2 * 2 + 1], ah[mt], bl[2], bl[3]);
                    MMA_BF16(acc[mt][nt2 * 2 + 1], al[mt], bh[2], bh[3]);
                }
            }
        }
    };

    LOADG(0);
    STORES(0);
    __syncthreads();

    for (int chunk = 0; chunk < NCHUNK; chunk++) {
        if (chunk + 1 < NCHUNK) LOADG((chunk + 1) * KC);   // overlaps with compute
        COMPUTE(chunk & 1);
        if (chunk + 1 < NCHUNK) STORES((chunk + 1) & 1);
        __syncthreads();
    }

    // epilogue: write fp32 accumulators
#pragma unroll
    for (int mt = 0; mt < 2; mt++) {
        const int row = m0 + wm * 32 + mt * 16 + (lane >> 2);
#pragma unroll
        for (int n = 0; n < 8; n++) {
            const int col = n0 + wn * 64 + n * 8 + (lane & 3) * 2;
            *(float2*)(C + (size_t)row * EMB + col) =
                make_float2(acc[mt][n][0], acc[mt][n][1]);
            *(float2*)(C + (size_t)(row + 8) * EMB + col) =
                make_float2(acc[mt][n][2], acc[mt][n][3]);
        }
    }
}

// ---------------- RoPE (in-place on Q and K, [S,E] layout) ----------------
__global__ void __launch_bounds__(64) rope_kernel(float* __restrict__ q, float* __restrict__ k)
{
    const int s = blockIdx.x;
    const int h = blockIdx.y;
    const int i = threadIdx.x;  // 0..63 pair index

    const float inv_freq = powf(10000.0f, -(float)i * (1.0f / 64.0f));
    const float ang = (float)s * inv_freq;
    const float c  = cosf(ang);
    const float sn = sinf(ang);

    const size_t base = (size_t)s * EMB + (size_t)h * HD;

    {
        float x0 = q[base + i], x1 = q[base + i + 64];
        q[base + i]      = x0 * c - x1 * sn;
        q[base + i + 64] = x1 * c + x0 * sn;
    }
    {
        float x0 = k[base + i], x1 = k[base + i + 64];
        k[base + i]      = x0 * c - x1 * sn;
        k[base + i + 64] = x1 * c + x0 * sn;
    }
}

// ---------------- fused flash attention: ctx = softmax(QK^T/sqrt(D)) @ V --------
#define FQT_STRIDE 68
#define FV_STRIDE  132
#define FSMEM_FLOATS (128*FQT_STRIDE*2 + 64*FV_STRIDE + 64*64)
#define FSMEM_BYTES  (FSMEM_FLOATS * 4)

__global__ void __launch_bounds__(256) flash_kernel(
    const float* __restrict__ q, const float* __restrict__ k,
    const float* __restrict__ v, float* __restrict__ ctx)
{
    extern __shared__ float fsm[];
    float* Qt = fsm;
    float* Kt = Qt + 128 * FQT_STRIDE;
    float* Vs = Kt + 128 * FQT_STRIDE;
    float* Ps = Vs + 64 * FV_STRIDE;

    const int t  = threadIdx.x;
    const int tx = t & 15;
    const int ty = t >> 4;
    const int h  = blockIdx.y;
    const int m0 = blockIdx.x * 64;
    const int hb = h * HD;
    const float SCALE = 0.08838834764831845f;

    for (int i = t; i < 64 * 32; i += 256) {
        const int row = i >> 5;
        const int cg  = (i & 31) << 2;
        float4 x = *(const float4*)(q + (size_t)(m0 + row) * EMB + hb + cg);
        Qt[(cg + 0) * FQT_STRIDE + row] = x.x;
        Qt[(cg + 1) * FQT_STRIDE + row] = x.y;
        Qt[(cg + 2) * FQT_STRIDE + row] = x.z;
        Qt[(cg + 3) * FQT_STRIDE + row] = x.w;
    }

    float o[4][8];
    float mrow[4], lrow[4];
#pragma unroll
    for (int i = 0; i < 4; i++) {
        mrow[i] = -1.0e30f;
        lrow[i] = 0.0f;
#pragma unroll
        for (int d = 0; d < 8; d++) o[i][d] = 0.0f;
    }
    __syncthreads();

    for (int kb = 0; kb < SEQ / 64; kb++) {
        const int n0 = kb * 64;
        for (int i = t; i < 64 * 32; i += 256) {
            const int row = i >> 5;
            const int cg  = (i & 31) << 2;
            float4 x = *(const float4*)(k + (size_t)(n0 + row) * EMB + hb + cg);
            Kt[(cg + 0) * FQT_STRIDE + row] = x.x;
            Kt[(cg + 1) * FQT_STRIDE + row] = x.y;
            Kt[(cg + 2) * FQT_STRIDE + row] = x.z;
            Kt[(cg + 3) * FQT_STRIDE + row] = x.w;
            float4 y = *(const float4*)(v + (size_t)(n0 + row) * EMB + hb + cg);
            *(float4*)&Vs[row * FV_STRIDE + cg] = y;
        }
        __syncthreads();

        float s[4][4];
#pragma unroll
        for (int i = 0; i < 4; i++)
#pragma unroll
            for (int j = 0; j < 4; j++) s[i][j] = 0.0f;

#pragma unroll 4
        for (int c = 0; c < 128; c++) {
            float4 a4 = *(const float4*)&Qt[c * FQT_STRIDE + ty * 4];
            float4 b4 = *(const float4*)&Kt[c * FQT_STRIDE + tx * 4];
            float a[4] = {a4.x, a4.y, a4.z, a4.w};
            float b[4] = {b4.x, b4.y, b4.z, b4.w};
#pragma unroll
            for (int i = 0; i < 4; i++)
#pragma unroll
                for (int j = 0; j < 4; j++) s[i][j] += a[i] * b[j];
        }

#pragma unroll
        for (int i = 0; i < 4; i++) {
            float mloc = fmaxf(fmaxf(s[i][0] * SCALE, s[i][1] * SCALE),
                               fmaxf(s[i][2] * SCALE, s[i][3] * SCALE));
#pragma unroll
            for (int off = 1; off < 16; off <<= 1)
                mloc = fmaxf(mloc, __shfl_xor_sync(0xffffffffu, mloc, off));
            const float mnew = fmaxf(mrow[i], mloc);
            const float corr = __expf(mrow[i] - mnew);
            float p[4], psum = 0.0f;
#pragma unroll
            for (int j = 0; j < 4; j++) {
                p[j] = __expf(s[i][j] * SCALE - mnew);
                psum += p[j];
            }
#pragma unroll
            for (int off = 1; off < 16; off <<= 1)
                psum += __shfl_xor_sync(0xffffffffu, psum, off);
            lrow[i] = lrow[i] * corr + psum;
            mrow[i] = mnew;
#pragma unroll
            for (int d = 0; d < 8; d++) o[i][d] *= corr;
#pragma unroll
            for (int j = 0; j < 4; j++)
                Ps[(ty * 4 + i) * 64 + tx * 4 + j] = p[j];
        }
        __syncthreads();

#pragma unroll 2
        for (int nn = 0; nn < 64; nn += 4) {
            float4 a[4];
#pragma unroll
            for (int i = 0; i < 4; i++)
                a[i] = *(const float4*)&Ps[(ty * 4 + i) * 64 + nn];
#pragma unroll
            for (int jj = 0; jj < 4; jj++) {
                float4 v0 = *(const float4*)&Vs[(nn + jj) * FV_STRIDE + tx * 8];
                float4 v1 = *(const float4*)&Vs[(nn + jj) * FV_STRIDE + tx * 8 + 4];
#pragma unroll
                for (int i = 0; i < 4; i++) {
                    const float av = (&a[i].x)[jj];
                    o[i][0] += av * v0.x; o[i][1] += av * v0.y;
                    o[i][2] += av * v0.z; o[i][3] += av * v0.w;
                    o[i][4] += av * v1.x; o[i][5] += av * v1.y;
                    o[i][6] += av * v1.z; o[i][7] += av * v1.w;
                }
            }
        }
        __syncthreads();
    }

#pragma unroll
    for (int i = 0; i < 4; i++) {
        const float inv = 1.0f / lrow[i];
        float4 w0, w1;
        w0.x = o[i][0] * inv; w0.y = o[i][1] * inv; w0.z = o[i][2] * inv; w0.w = o[i][3] * inv;
        w1.x = o[i][4] * inv; w1.y = o[i][5] * inv; w1.z = o[i][6] * inv; w1.w = o[i][7] * inv;
        float* dst = ctx + (size_t)(m0 + ty * 4 + i) * EMB + hb + tx * 8;
        *(float4*)dst = w0;
        *(float4*)(dst + 4) = w1;
    }
}

// ---------------- launch ----------------
extern "C" void kernel_launch(void* const* d_in, const int* in_sizes, int n_in,
                              void* d_out, int out_size)
{
    const float* hs = (const float*)d_in[0];
    const float* Wq = (const float*)d_in[1];
    const float* Wk = (const float*)d_in[2];
    const float* Wv = (const float*)d_in[3];
    const float* Wo = (const float*)d_in[4];
    float* out = (float*)d_out;

    float *q, *k, *v, *ctx;
    cudaGetSymbolAddress((void**)&q,   g_q);
    cudaGetSymbolAddress((void**)&k,   g_k);
    cudaGetSymbolAddress((void**)&v,   g_v);
    cudaGetSymbolAddress((void**)&ctx, g_ctx);

    cudaFuncSetAttribute(gemm_mma,     cudaFuncAttributeMaxDynamicSharedMemorySize, GSM_BYTES);
    cudaFuncSetAttribute(flash_kernel, cudaFuncAttributeMaxDynamicSharedMemorySize, FSMEM_BYTES);

    // fused QKV: one launch, z selects weight/output
    gemm_mma<<<dim3(EMB / 128, SEQ / 128, 3), 256, GSM_BYTES>>>(hs, Wq, Wk, Wv, q, k, v);

    rope_kernel<<<dim3(SEQ, NH), 64>>>(q, k);

    flash_kernel<<<dim3(SEQ / 64, NH), 256, FSMEM_BYTES>>>(q, k, v, ctx);

    // output projection
    gemm_mma<<<dim3(EMB / 128, SEQ / 128, 1), 256, GSM_BYTES>>>(ctx, Wo, Wo, Wo, out, out, out);
}

// round 7
// speedup vs baseline: 3.1497x; 2.1350x over previous
#include <cuda_runtime.h>
#include <cuda_bf16.h>
#include <cstdint>
#include <math.h>

#define SEQ  2048
#define EMB  2048
#define NH   16
#define HD   128

// ---------------- scratch (allocation-free: static device globals) ----------------
__device__ float g_q[(size_t)SEQ * EMB];
__device__ float g_k[(size_t)SEQ * EMB];
__device__ float g_v[(size_t)SEQ * EMB];
__device__ float g_ctx[(size_t)SEQ * EMB];
// bf16 splits (RoPE + scale folded into q)
__device__ __nv_bfloat16 g_qh[(size_t)SEQ * EMB];
__device__ __nv_bfloat16 g_ql[(size_t)SEQ * EMB];
__device__ __nv_bfloat16 g_kh[(size_t)SEQ * EMB];
__device__ __nv_bfloat16 g_kl[(size_t)SEQ * EMB];
// V transposed per head: vt[(h*128+d)*SEQ + s]
__device__ __nv_bfloat16 g_vth[(size_t)EMB * SEQ];
__device__ __nv_bfloat16 g_vtl[(size_t)EMB * SEQ];

// ======================= warp-MMA helpers ==============
__device__ __forceinline__ uint32_t smem_u32(const void* p) {
    uint32_t a;
    asm("{ .reg .u64 t; cvta.to.shared.u64 t, %1; cvt.u32.u64 %0, t; }" : "=r"(a) : "l"(p));
    return a;
}
#define LDSM4(r0, r1, r2, r3, addr)                                               \
    asm volatile("ldmatrix.sync.aligned.m8n8.x4.shared.b16 {%0,%1,%2,%3}, [%4];"  \
        : "=r"(r0), "=r"(r1), "=r"(r2), "=r"(r3) : "r"(addr))
#define MMA_BF16(c, a, b0, b1)                                                    \
    asm volatile("mma.sync.aligned.m16n8k16.row.col.f32.bf16.bf16.f32 "           \
        "{%0,%1,%2,%3}, {%4,%5,%6,%7}, {%8,%9}, {%0,%1,%2,%3};"                   \
        : "+f"((c)[0]), "+f"((c)[1]), "+f"((c)[2]), "+f"((c)[3])                  \
        : "r"((a)[0]), "r"((a)[1]), "r"((a)[2]), "r"((a)[3]), "r"(b0), "r"(b1))

__device__ __forceinline__ void split_bf16(float x, __nv_bfloat16& h, __nv_bfloat16& l) {
    h = __float2bfloat16(x);
    l = __float2bfloat16(x - __bfloat162float(h));
}

// ============ HMMA NT GEMM: C = A @ B^T, split-bf16 3-term (unchanged from R6) ===
#define KC      32
#define NCHUNK  (EMB / KC)
#define RSTRIDE 40
#define BUF_E   (128 * RSTRIDE)
#define STAGE_E (4 * BUF_E)
#define GSM_BYTES (2 * STAGE_E * 2)

__global__ void __launch_bounds__(256) gemm_mma(
    const float* __restrict__ A,
    const float* __restrict__ B0, const float* __restrict__ B1, const float* __restrict__ B2,
    float* __restrict__ C0, float* __restrict__ C1, float* __restrict__ C2)
{
    const float* B = (blockIdx.z == 0) ? B0 : (blockIdx.z == 1) ? B1 : B2;
    float*       C = (blockIdx.z == 0) ? C0 : (blockIdx.z == 1) ? C1 : C2;

    extern __shared__ __align__(16) __nv_bfloat16 sm[];

    const int t    = threadIdx.x;
    const int lane = t & 31;
    const int wid  = t >> 5;
    const int wm   = wid & 3;
    const int wn   = wid >> 2;
    const int m0   = blockIdx.y * 128;
    const int n0   = blockIdx.x * 128;
    const int id   = lane >> 3;
    const int r8   = lane & 7;

    float acc[2][8][4];
#pragma unroll
    for (int i = 0; i < 2; i++)
#pragma unroll
        for (int j = 0; j < 8; j++)
#pragma unroll
            for (int c = 0; c < 4; c++) acc[i][j][c] = 0.0f;

    float4 pref[8];

    auto LOADG = [&](int k0) {
#pragma unroll
        for (int j = 0; j < 4; j++) {
            const int idx = j * 256 + t;
            const int row = idx >> 3;
            const int cg  = (idx & 7) << 2;
            pref[j]     = *(const float4*)(A + (size_t)(m0 + row) * EMB + k0 + cg);
            pref[4 + j] = *(const float4*)(B + (size_t)(n0 + row) * EMB + k0 + cg);
        }
    };
    auto STORES = [&](int s) {
        __nv_bfloat16* st = sm + s * STAGE_E;
#pragma unroll
        for (int mat = 0; mat < 2; mat++) {
            __nv_bfloat16* dh = st + (mat ? 2 * BUF_E : 0);
            __nv_bfloat16* dl = dh + BUF_E;
#pragma unroll
            for (int j = 0; j < 4; j++) {
                const int idx = j * 256 + t;
                const int row = idx >> 3;
                const int cg  = (idx & 7) << 2;
                float4 x = pref[mat * 4 + j];
                __nv_bfloat16 h0, h1, h2, h3, l0, l1, l2, l3;
                split_bf16(x.x, h0, l0); split_bf16(x.y, h1, l1);
                split_bf16(x.z, h2, l2); split_bf16(x.w, h3, l3);
                __nv_bfloat162 hp0 = __halves2bfloat162(h0, h1);
                __nv_bfloat162 hp1 = __halves2bfloat162(h2, h3);
                __nv_bfloat162 lp0 = __halves2bfloat162(l0, l1);
                __nv_bfloat162 lp1 = __halves2bfloat162(l2, l3);
                const int o = row * RSTRIDE + cg;
                *(uint2*)(dh + o) = make_uint2(*(uint32_t*)&hp0, *(uint32_t*)&hp1);
                *(uint2*)(dl + o) = make_uint2(*(uint32_t*)&lp0, *(uint32_t*)&lp1);
            }
        }
    };
    auto COMPUTE = [&](int s) {
        const uint32_t uAh = smem_u32(sm + s * STAGE_E);
        const uint32_t uAl = uAh + BUF_E * 2;
        const uint32_t uBh = uAl + BUF_E * 2;
        const uint32_t uBl = uBh + BUF_E * 2;
#pragma unroll
        for (int kk = 0; kk < KC; kk += 16) {
            uint32_t ah[2][4], al[2][4];
#pragma unroll
            for (int mt = 0; mt < 2; mt++) {
                const uint32_t offA =
                    ((wm * 32 + mt * 16 + (id & 1) * 8 + r8) * RSTRIDE + kk + (id >> 1) * 8) * 2;
                LDSM4(ah[mt][0], ah[mt][1], ah[mt][2], ah[mt][3], uAh + offA);
                LDSM4(al[mt][0], al[mt][1], al[mt][2], al[mt][3], uAl + offA);
            }
#pragma unroll
            for (int nt2 = 0; nt2 < 4; nt2++) {
                const uint32_t offB =
                    ((wn * 64 + nt2 * 16 + (id >> 1) * 8 + r8) * RSTRIDE + kk + (id & 1) * 8) * 2;
                uint32_t bh[4], bl[4];
                LDSM4(bh[0], bh[1], bh[2], bh[3], uBh + offB);
                LDSM4(bl[0], bl[1], bl[2], bl[3], uBl + offB);
#pragma unroll
                for (int mt = 0; mt < 2; mt++) {
                    MMA_BF16(acc[mt][nt2 * 2],     ah[mt], bh[0], bh[1]);
                    MMA_BF16(acc[mt][nt2 * 2],     ah[mt], bl[0], bl[1]);
                    MMA_BF16(acc[mt][nt2 * 2],     al[mt], bh[0], bh[1]);
                    MMA_BF16(acc[mt][nt2 * 2 + 1], ah[mt], bh[2], bh[3]);
                    MMA_BF16(acc[mt][nt2 * 2 + 1], ah[mt], bl[2], bl[3]);
                    MMA_BF16(acc[mt][nt2 * 2 + 1], al[mt], bh[2], bh[3]);
                }
            }
        }
    };

    LOADG(0);
    STORES(0);
    __syncthreads();

    for (int chunk = 0; chunk < NCHUNK; chunk++) {
        if (chunk + 1 < NCHUNK) LOADG((chunk + 1) * KC);
        COMPUTE(chunk & 1);
        if (chunk + 1 < NCHUNK) STORES((chunk + 1) & 1);
        __syncthreads();
    }

#pragma unroll
    for (int mt = 0; mt < 2; mt++) {
        const int row = m0 + wm * 32 + mt * 16 + (lane >> 2);
#pragma unroll
        for (int n = 0; n < 8; n++) {
            const int col = n0 + wn * 64 + n * 8 + (lane & 3) * 2;
            *(float2*)(C + (size_t)row * EMB + col) =
                make_float2(acc[mt][n][0], acc[mt][n][1]);
            *(float2*)(C + (size_t)(row + 8) * EMB + col) =
                make_float2(acc[mt][n][2], acc[mt][n][3]);
        }
    }
}

// ---------- RoPE + scale + split-convert: fp32 q,k -> qh/ql (scaled), kh/kl ------
__global__ void __launch_bounds__(64) rope_convert(
    const float* __restrict__ q, const float* __restrict__ k,
    __nv_bfloat16* __restrict__ qh, __nv_bfloat16* __restrict__ ql,
    __nv_bfloat16* __restrict__ kh, __nv_bfloat16* __restrict__ kl)
{
    const int s = blockIdx.x;
    const int h = blockIdx.y;
    const int i = threadIdx.x;  // 0..63 pair
    const float SCALE = 0.08838834764831845f;

    const float inv_freq = powf(10000.0f, -(float)i * (1.0f / 64.0f));
    const float ang = (float)s * inv_freq;
    const float c  = cosf(ang);
    const float sn = sinf(ang);

    const size_t base = (size_t)s * EMB + (size_t)h * HD;

    {
        float x0 = q[base + i], x1 = q[base + i + 64];
        float r0 = (x0 * c - x1 * sn) * SCALE;
        float r1 = (x1 * c + x0 * sn) * SCALE;
        __nv_bfloat16 h0, l0, h1, l1;
        split_bf16(r0, h0, l0); split_bf16(r1, h1, l1);
        qh[base + i] = h0;      ql[base + i] = l0;
        qh[base + i + 64] = h1; ql[base + i + 64] = l1;
    }
    {
        float x0 = k[base + i], x1 = k[base + i + 64];
        float r0 = x0 * c - x1 * sn;
        float r1 = x1 * c + x0 * sn;
        __nv_bfloat16 h0, l0, h1, l1;
        split_bf16(r0, h0, l0); split_bf16(r1, h1, l1);
        kh[base + i] = h0;      kl[base + i] = l0;
        kh[base + i + 64] = h1; kl[base + i + 64] = l1;
    }
}

// ---------- V transpose + split: v[s][e] -> vt[e][s] (bf16 hi/lo) --------------
__global__ void __launch_bounds__(256) vtrans(
    const float* __restrict__ v,
    __nv_bfloat16* __restrict__ vth, __nv_bfloat16* __restrict__ vtl)
{
    __shared__ float tile[32][33];
    const int s0 = blockIdx.x * 32;
    const int e0 = blockIdx.y * 32;
    const int tx = threadIdx.x & 31;
    const int ty = threadIdx.x >> 5;   // 0..7

#pragma unroll
    for (int j = 0; j < 4; j++) {
        const int r = ty + j * 8;
        tile[r][tx] = v[(size_t)(s0 + r) * EMB + e0 + tx];
    }
    __syncthreads();
#pragma unroll
    for (int j = 0; j < 4; j++) {
        const int el = ty + j * 8;
        const float x = tile[tx][el];
        __nv_bfloat16 h, l;
        split_bf16(x, h, l);
        const size_t o = (size_t)(e0 + el) * SEQ + s0 + tx;
        vth[o] = h;
        vtl[o] = l;
    }
}

// ---------------- flash attention with HMMA (split-bf16 3-term both GEMMs) ------
// CTA: 128 q-rows x 1 head. 8 warps (wm 0..3 rows band 32, wn 0..1).
// K blocks of 64. Online softmax, O in fp32 registers.
#define QSTRIDE 136
#define KSTRIDE 136
#define VSTRIDE 72
#define PSTRIDE 72
// bf16-element offsets in smem
#define QHo 0
#define QLo (128 * QSTRIDE)
#define KHo (2 * 128 * QSTRIDE)
#define KLo (KHo + 64 * KSTRIDE)
#define VHo (KHo + 2 * 64 * KSTRIDE)
#define VLo (VHo + 128 * VSTRIDE)
#define PHo (VHo + 2 * 128 * VSTRIDE)
#define PLo (PHo + 128 * PSTRIDE)
#define FB16_TOTAL (PHo + 2 * 128 * PSTRIDE)
#define FRED_OFF   (FB16_TOTAL * 2)                  // bytes
#define FSMEM_BYTES (FRED_OFF + 2 * 2 * 128 * 4)     // + pmax/psum [2][128] floats

__global__ void __launch_bounds__(256) flash_mma(
    const __nv_bfloat16* __restrict__ qh, const __nv_bfloat16* __restrict__ ql,
    const __nv_bfloat16* __restrict__ kh, const __nv_bfloat16* __restrict__ kl,
    const __nv_bfloat16* __restrict__ vth, const __nv_bfloat16* __restrict__ vtl,
    float* __restrict__ ctx)
{
    extern __shared__ __align__(16) __nv_bfloat16 fs[];
    float* pmax = (float*)((char*)fs + FRED_OFF);        // [2][128]
    float* psum = pmax + 256;                             // [2][128]

    const int t    = threadIdx.x;
    const int lane = t & 31;
    const int wid  = t >> 5;
    const int wm   = wid & 3;
    const int wn   = wid >> 2;
    const int id   = lane >> 3;
    const int r8   = lane & 7;
    const int h    = blockIdx.y;
    const int m0   = blockIdx.x * 128;
    const int hb   = h * HD;

    const uint32_t uQH = smem_u32(fs + QHo);
    const uint32_t uQL = smem_u32(fs + QLo);
    const uint32_t uKH = smem_u32(fs + KHo);
    const uint32_t uKL = smem_u32(fs + KLo);
    const uint32_t uVH = smem_u32(fs + VHo);
    const uint32_t uVL = smem_u32(fs + VLo);
    const uint32_t uPH = smem_u32(fs + PHo);
    const uint32_t uPL = smem_u32(fs + PLo);

    // ---- load Q tile once (scaled, roped, split) ----
#pragma unroll
    for (int j = 0; j < 8; j++) {
        const int idx = j * 256 + t;
        const int r = idx >> 4;
        const int c = (idx & 15) * 8;
        *(uint4*)(fs + QHo + r * QSTRIDE + c) =
            *(const uint4*)(qh + (size_t)(m0 + r) * EMB + hb + c);
        *(uint4*)(fs + QLo + r * QSTRIDE + c) =
            *(const uint4*)(ql + (size_t)(m0 + r) * EMB + hb + c);
    }

    float acc_o[2][8][4];
#pragma unroll
    for (int i = 0; i < 2; i++)
#pragma unroll
        for (int j = 0; j < 8; j++)
#pragma unroll
            for (int c = 0; c < 4; c++) acc_o[i][j][c] = 0.0f;
    float m_r[2][2], l_r[2][2];
#pragma unroll
    for (int i = 0; i < 2; i++) { m_r[i][0] = m_r[i][1] = -1.0e30f; l_r[i][0] = l_r[i][1] = 0.0f; }

    for (int kb = 0; kb < SEQ / 64; kb++) {
        const int n0 = kb * 64;
        __syncthreads();   // prior PV mma done with K/V/P smem

        // ---- load K (64x128) and Vt (128x64) tiles ----
#pragma unroll
        for (int j = 0; j < 4; j++) {
            const int idx = j * 256 + t;
            {
                const int r = idx >> 4;
                const int c = (idx & 15) * 8;
                *(uint4*)(fs + KHo + r * KSTRIDE + c) =
                    *(const uint4*)(kh + (size_t)(n0 + r) * EMB + hb + c);
                *(uint4*)(fs + KLo + r * KSTRIDE + c) =
                    *(const uint4*)(kl + (size_t)(n0 + r) * EMB + hb + c);
            }
            {
                const int r = idx >> 3;
                const int c = (idx & 7) * 8;
                *(uint4*)(fs + VHo + r * VSTRIDE + c) =
                    *(const uint4*)(vth + (size_t)(hb + r) * SEQ + n0 + c);
                *(uint4*)(fs + VLo + r * VSTRIDE + c) =
                    *(const uint4*)(vtl + (size_t)(hb + r) * SEQ + n0 + c);
            }
        }
        __syncthreads();

        // ---- S = Q @ K^T (3-term), warp tile 32x32 ----
        float acc_s[2][4][4];
#pragma unroll
        for (int i = 0; i < 2; i++)
#pragma unroll
            for (int j = 0; j < 4; j++)
#pragma unroll
                for (int c = 0; c < 4; c++) acc_s[i][j][c] = 0.0f;

#pragma unroll
        for (int kk = 0; kk < 128; kk += 16) {
            uint32_t ah[2][4], al[2][4];
#pragma unroll
            for (int mt = 0; mt < 2; mt++) {
                const uint32_t offA =
                    ((wm * 32 + mt * 16 + (id & 1) * 8 + r8) * QSTRIDE + kk + (id >> 1) * 8) * 2;
                LDSM4(ah[mt][0], ah[mt][1], ah[mt][2], ah[mt][3], uQH + offA);
                LDSM4(al[mt][0], al[mt][1], al[mt][2], al[mt][3], uQL + offA);
            }
#pragma unroll
            for (int nt2 = 0; nt2 < 2; nt2++) {
                const uint32_t offB =
                    ((wn * 32 + nt2 * 16 + (id >> 1) * 8 + r8) * KSTRIDE + kk + (id & 1) * 8) * 2;
                uint32_t bh[4], bl[4];
                LDSM4(bh[0], bh[1], bh[2], bh[3], uKH + offB);
                LDSM4(bl[0], bl[1], bl[2], bl[3], uKL + offB);
#pragma unroll
                for (int mt = 0; mt < 2; mt++) {
                    MMA_BF16(acc_s[mt][nt2 * 2],     ah[mt], bh[0], bh[1]);
                    MMA_BF16(acc_s[mt][nt2 * 2],     ah[mt], bl[0], bl[1]);
                    MMA_BF16(acc_s[mt][nt2 * 2],     al[mt], bh[0], bh[1]);
                    MMA_BF16(acc_s[mt][nt2 * 2 + 1], ah[mt], bh[2], bh[3]);
                    MMA_BF16(acc_s[mt][nt2 * 2 + 1], ah[mt], bl[2], bl[3]);
                    MMA_BF16(acc_s[mt][nt2 * 2 + 1], al[mt], bh[2], bh[3]);
                }
            }
        }

        // ---- online softmax (rows shared across wn warps via smem partials) ----
#pragma unroll
        for (int mt = 0; mt < 2; mt++)
#pragma unroll
            for (int hf = 0; hf < 2; hf++) {
                float mx = -1.0e30f;
#pragma unroll
                for (int nt = 0; nt < 4; nt++)
                    mx = fmaxf(mx, fmaxf(acc_s[mt][nt][hf * 2], acc_s[mt][nt][hf * 2 + 1]));
                mx = fmaxf(mx, __shfl_xor_sync(0xffffffffu, mx, 1));
                mx = fmaxf(mx, __shfl_xor_sync(0xffffffffu, mx, 2));
                const int row = wm * 32 + mt * 16 + hf * 8 + (lane >> 2);
                if ((lane & 3) == 0) pmax[wn * 128 + row] = mx;
            }
        __syncthreads();

        float corr_s[2][2];
#pragma unroll
        for (int mt = 0; mt < 2; mt++)
#pragma unroll
            for (int hf = 0; hf < 2; hf++) {
                const int row = wm * 32 + mt * 16 + hf * 8 + (lane >> 2);
                const float mb = fmaxf(pmax[row], pmax[128 + row]);
                const float mn = fmaxf(m_r[mt][hf], mb);
                const float corr = __expf(m_r[mt][hf] - mn);
                corr_s[mt][hf] = corr;
                m_r[mt][hf] = mn;
                float ps = 0.0f;
#pragma unroll
                for (int nt = 0; nt < 4; nt++) {
                    float p0 = __expf(acc_s[mt][nt][hf * 2]     - mn);
                    float p1 = __expf(acc_s[mt][nt][hf * 2 + 1] - mn);
                    ps += p0 + p1;
                    __nv_bfloat16 h0, l0, h1, l1;
                    split_bf16(p0, h0, l0); split_bf16(p1, h1, l1);
                    __nv_bfloat162 hp = __halves2bfloat162(h0, h1);
                    __nv_bfloat162 lp = __halves2bfloat162(l0, l1);
                    const int col = wn * 32 + nt * 8 + (lane & 3) * 2;
                    *(uint32_t*)(fs + PHo + row * PSTRIDE + col) = *(uint32_t*)&hp;
                    *(uint32_t*)(fs + PLo + row * PSTRIDE + col) = *(uint32_t*)&lp;
                }
                ps += __shfl_xor_sync(0xffffffffu, ps, 1);
                ps += __shfl_xor_sync(0xffffffffu, ps, 2);
                if ((lane & 3) == 0) psum[wn * 128 + row] = ps;
                // rescale O accumulators for these rows
#pragma unroll
                for (int nt = 0; nt < 8; nt++) {
                    acc_o[mt][nt][hf * 2]     *= corr;
                    acc_o[mt][nt][hf * 2 + 1] *= corr;
                }
            }
        __syncthreads();

#pragma unroll
        for (int mt = 0; mt < 2; mt++)
#pragma unroll
            for (int hf = 0; hf < 2; hf++) {
                const int row = wm * 32 + mt * 16 + hf * 8 + (lane >> 2);
                l_r[mt][hf] = l_r[mt][hf] * corr_s[mt][hf] + psum[row] + psum[128 + row];
            }

        // ---- O += P @ V (3-term), warp tile 32 x 64 (d) ----
#pragma unroll
        for (int kk = 0; kk < 64; kk += 16) {
            uint32_t pa[2][4], pl[2][4];
#pragma unroll
            for (int mt = 0; mt < 2; mt++) {
                const uint32_t offA =
                    ((wm * 32 + mt * 16 + (id & 1) * 8 + r8) * PSTRIDE + kk + (id >> 1) * 8) * 2;
                LDSM4(pa[mt][0], pa[mt][1], pa[mt][2], pa[mt][3], uPH + offA);
                LDSM4(pl[mt][0], pl[mt][1], pl[mt][2], pl[mt][3], uPL + offA);
            }
#pragma unroll
            for (int nt2 = 0; nt2 < 4; nt2++) {
                const uint32_t offB =
                    ((wn * 64 + nt2 * 16 + (id >> 1) * 8 + r8) * VSTRIDE + kk + (id & 1) * 8) * 2;
                uint32_t bh[4], bl[4];
                LDSM4(bh[0], bh[1], bh[2], bh[3], uVH + offB);
                LDSM4(bl[0], bl[1], bl[2], bl[3], uVL + offB);
#pragma unroll
                for (int mt = 0; mt < 2; mt++) {
                    MMA_BF16(acc_o[mt][nt2 * 2],     pa[mt], bh[0], bh[1]);
                    MMA_BF16(acc_o[mt][nt2 * 2],     pa[mt], bl[0], bl[1]);
                    MMA_BF16(acc_o[mt][nt2 * 2],     pl[mt], bh[0], bh[1]);
                    MMA_BF16(acc_o[mt][nt2 * 2 + 1], pa[mt], bh[2], bh[3]);
                    MMA_BF16(acc_o[mt][nt2 * 2 + 1], pa[mt], bl[2], bl[3]);
                    MMA_BF16(acc_o[mt][nt2 * 2 + 1], pl[mt], bh[2], bh[3]);
                }
            }
        }
    }

    // ---- epilogue: normalize and write ctx ----
#pragma unroll
    for (int mt = 0; mt < 2; mt++)
#pragma unroll
        for (int hf = 0; hf < 2; hf++) {
            const float inv = 1.0f / l_r[mt][hf];
            const int row = m0 + wm * 32 + mt * 16 + hf * 8 + (lane >> 2);
#pragma unroll
            for (int nt = 0; nt < 8; nt++) {
                const int col = hb + wn * 64 + nt * 8 + (lane & 3) * 2;
                *(float2*)(ctx + (size_t)row * EMB + col) =
                    make_float2(acc_o[mt][nt][hf * 2] * inv, acc_o[mt][nt][hf * 2 + 1] * inv);
            }
        }
}

// ---------------- launch ----------------
extern "C" void kernel_launch(void* const* d_in, const int* in_sizes, int n_in,
                              void* d_out, int out_size)
{
    const float* hs = (const float*)d_in[0];
    const float* Wq = (const float*)d_in[1];
    const float* Wk = (const float*)d_in[2];
    const float* Wv = (const float*)d_in[3];
    const float* Wo = (const float*)d_in[4];
    float* out = (float*)d_out;

    float *q, *k, *v, *ctx;
    __nv_bfloat16 *qh, *ql, *kh, *kl, *vth, *vtl;
    cudaGetSymbolAddress((void**)&q,   g_q);
    cudaGetSymbolAddress((void**)&k,   g_k);
    cudaGetSymbolAddress((void**)&v,   g_v);
    cudaGetSymbolAddress((void**)&ctx, g_ctx);
    cudaGetSymbolAddress((void**)&qh,  g_qh);
    cudaGetSymbolAddress((void**)&ql,  g_ql);
    cudaGetSymbolAddress((void**)&kh,  g_kh);
    cudaGetSymbolAddress((void**)&kl,  g_kl);
    cudaGetSymbolAddress((void**)&vth, g_vth);
    cudaGetSymbolAddress((void**)&vtl, g_vtl);

    cudaFuncSetAttribute(gemm_mma,  cudaFuncAttributeMaxDynamicSharedMemorySize, GSM_BYTES);
    cudaFuncSetAttribute(flash_mma, cudaFuncAttributeMaxDynamicSharedMemorySize, FSMEM_BYTES);

    gemm_mma<<<dim3(EMB / 128, SEQ / 128, 3), 256, GSM_BYTES>>>(hs, Wq, Wk, Wv, q, k, v);

    rope_convert<<<dim3(SEQ, NH), 64>>>(q, k, qh, ql, kh, kl);
    vtrans<<<dim3(SEQ / 32, EMB / 32), 256>>>(v, vth, vtl);

    flash_mma<<<dim3(SEQ / 128, NH), 256, FSMEM_BYTES>>>(qh, ql, kh, kl, vth, vtl, ctx);

    gemm_mma<<<dim3(EMB / 128, SEQ / 128, 1), 256, GSM_BYTES>>>(ctx, Wo, Wo, Wo, out, out, out);
}

// round 8
// speedup vs baseline: 3.2265x; 1.0244x over previous
#include <cuda_runtime.h>
#include <cuda_bf16.h>
#include <cstdint>
#include <math.h>

#define SEQ  2048
#define EMB  2048
#define NH   16
#define HD   128

// ---------------- scratch (allocation-free: static device globals) ----------------
__device__ float g_q[(size_t)SEQ * EMB];
__device__ float g_k[(size_t)SEQ * EMB];
__device__ float g_v[(size_t)SEQ * EMB];
__device__ float g_ctx[(size_t)SEQ * EMB];
__device__ __nv_bfloat16 g_qh[(size_t)SEQ * EMB];
__device__ __nv_bfloat16 g_ql[(size_t)SEQ * EMB];
__device__ __nv_bfloat16 g_kh[(size_t)SEQ * EMB];
__device__ __nv_bfloat16 g_kl[(size_t)SEQ * EMB];
__device__ __nv_bfloat16 g_vth[(size_t)EMB * SEQ];
__device__ __nv_bfloat16 g_vtl[(size_t)EMB * SEQ];

// ======================= warp-MMA helpers ==============
__device__ __forceinline__ uint32_t smem_u32(const void* p) {
    uint32_t a;
    asm("{ .reg .u64 t; cvta.to.shared.u64 t, %1; cvt.u32.u64 %0, t; }" : "=r"(a) : "l"(p));
    return a;
}
#define LDSM4(r0, r1, r2, r3, addr)                                               \
    asm volatile("ldmatrix.sync.aligned.m8n8.x4.shared.b16 {%0,%1,%2,%3}, [%4];"  \
        : "=r"(r0), "=r"(r1), "=r"(r2), "=r"(r3) : "r"(addr))
#define MMA_BF16(c, a, b0, b1)                                                    \
    asm volatile("mma.sync.aligned.m16n8k16.row.col.f32.bf16.bf16.f32 "           \
        "{%0,%1,%2,%3}, {%4,%5,%6,%7}, {%8,%9}, {%0,%1,%2,%3};"                   \
        : "+f"((c)[0]), "+f"((c)[1]), "+f"((c)[2]), "+f"((c)[3])                  \
        : "r"((a)[0]), "r"((a)[1]), "r"((a)[2]), "r"((a)[3]), "r"(b0), "r"(b1))

__device__ __forceinline__ void split_bf16(float x, __nv_bfloat16& h, __nv_bfloat16& l) {
    h = __float2bfloat16(x);
    l = __float2bfloat16(x - __bfloat162float(h));
}

// ============ HMMA NT GEMM, 512 threads (16 warps, warp tile 32x32) ============
#define KC      32
#define NCHUNK  (EMB / KC)
#define RSTRIDE 40
#define BUF_E   (128 * RSTRIDE)
#define STAGE_E (4 * BUF_E)
#define GSM_BYTES (2 * STAGE_E * 2)

__global__ void __launch_bounds__(512, 1) gemm_mma(
    const float* __restrict__ A,
    const float* __restrict__ B0, const float* __restrict__ B1, const float* __restrict__ B2,
    float* __restrict__ C0, float* __restrict__ C1, float* __restrict__ C2)
{
    const float* B = (blockIdx.z == 0) ? B0 : (blockIdx.z == 1) ? B1 : B2;
    float*       C = (blockIdx.z == 0) ? C0 : (blockIdx.z == 1) ? C1 : C2;

    extern __shared__ __align__(16) __nv_bfloat16 sm[];

    const int t    = threadIdx.x;
    const int lane = t & 31;
    const int wid  = t >> 5;           // 0..15
    const int wm   = wid & 3;          // 32-row band
    const int wn   = wid >> 2;         // 0..3  -> 32-col band
    const int m0   = blockIdx.y * 128;
    const int n0   = blockIdx.x * 128;
    const int id   = lane >> 3;
    const int r8   = lane & 7;

    float acc[2][4][4];
#pragma unroll
    for (int i = 0; i < 2; i++)
#pragma unroll
        for (int j = 0; j < 4; j++)
#pragma unroll
            for (int c = 0; c < 4; c++) acc[i][j][c] = 0.0f;

    float4 pref[4];

    auto LOADG = [&](int k0) {
#pragma unroll
        for (int j = 0; j < 2; j++) {
            const int idx = j * 512 + t;       // 0..1023
            const int row = idx >> 3;
            const int cg  = (idx & 7) << 2;
            pref[j]     = *(const float4*)(A + (size_t)(m0 + row) * EMB + k0 + cg);
            pref[2 + j] = *(const float4*)(B + (size_t)(n0 + row) * EMB + k0 + cg);
        }
    };
    auto STORES = [&](int s) {
        __nv_bfloat16* st = sm + s * STAGE_E;
#pragma unroll
        for (int mat = 0; mat < 2; mat++) {
            __nv_bfloat16* dh = st + (mat ? 2 * BUF_E : 0);
            __nv_bfloat16* dl = dh + BUF_E;
#pragma unroll
            for (int j = 0; j < 2; j++) {
                const int idx = j * 512 + t;
                const int row = idx >> 3;
                const int cg  = (idx & 7) << 2;
                float4 x = pref[mat * 2 + j];
                __nv_bfloat16 h0, h1, h2, h3, l0, l1, l2, l3;
                split_bf16(x.x, h0, l0); split_bf16(x.y, h1, l1);
                split_bf16(x.z, h2, l2); split_bf16(x.w, h3, l3);
                __nv_bfloat162 hp0 = __halves2bfloat162(h0, h1);
                __nv_bfloat162 hp1 = __halves2bfloat162(h2, h3);
                __nv_bfloat162 lp0 = __halves2bfloat162(l0, l1);
                __nv_bfloat162 lp1 = __halves2bfloat162(l2, l3);
                const int o = row * RSTRIDE + cg;
                *(uint2*)(dh + o) = make_uint2(*(uint32_t*)&hp0, *(uint32_t*)&hp1);
                *(uint2*)(dl + o) = make_uint2(*(uint32_t*)&lp0, *(uint32_t*)&lp1);
            }
        }
    };
    auto COMPUTE = [&](int s) {
        const uint32_t uAh = smem_u32(sm + s * STAGE_E);
        const uint32_t uAl = uAh + BUF_E * 2;
        const uint32_t uBh = uAl + BUF_E * 2;
        const uint32_t uBl = uBh + BUF_E * 2;
#pragma unroll
        for (int kk = 0; kk < KC; kk += 16) {
            uint32_t ah[2][4], al[2][4];
#pragma unroll
            for (int mt = 0; mt < 2; mt++) {
                const uint32_t offA =
                    ((wm * 32 + mt * 16 + (id & 1) * 8 + r8) * RSTRIDE + kk + (id >> 1) * 8) * 2;
                LDSM4(ah[mt][0], ah[mt][1], ah[mt][2], ah[mt][3], uAh + offA);
                LDSM4(al[mt][0], al[mt][1], al[mt][2], al[mt][3], uAl + offA);
            }
#pragma unroll
            for (int nt2 = 0; nt2 < 2; nt2++) {
                const uint32_t offB =
                    ((wn * 32 + nt2 * 16 + (id >> 1) * 8 + r8) * RSTRIDE + kk + (id & 1) * 8) * 2;
                uint32_t bh[4], bl[4];
                LDSM4(bh[0], bh[1], bh[2], bh[3], uBh + offB);
                LDSM4(bl[0], bl[1], bl[2], bl[3], uBl + offB);
#pragma unroll
                for (int mt = 0; mt < 2; mt++) {
                    MMA_BF16(acc[mt][nt2 * 2],     ah[mt], bh[0], bh[1]);
                    MMA_BF16(acc[mt][nt2 * 2],     ah[mt], bl[0], bl[1]);
                    MMA_BF16(acc[mt][nt2 * 2],     al[mt], bh[0], bh[1]);
                    MMA_BF16(acc[mt][nt2 * 2 + 1], ah[mt], bh[2], bh[3]);
                    MMA_BF16(acc[mt][nt2 * 2 + 1], ah[mt], bl[2], bl[3]);
                    MMA_BF16(acc[mt][nt2 * 2 + 1], al[mt], bh[2], bh[3]);
                }
            }
        }
    };

    LOADG(0);
    STORES(0);
    __syncthreads();

    for (int chunk = 0; chunk < NCHUNK; chunk++) {
        if (chunk + 1 < NCHUNK) LOADG((chunk + 1) * KC);
        COMPUTE(chunk & 1);
        if (chunk + 1 < NCHUNK) STORES((chunk + 1) & 1);
        __syncthreads();
    }

#pragma unroll
    for (int mt = 0; mt < 2; mt++) {
        const int row = m0 + wm * 32 + mt * 16 + (lane >> 2);
#pragma unroll
        for (int n = 0; n < 4; n++) {
            const int col = n0 + wn * 32 + n * 8 + (lane & 3) * 2;
            *(float2*)(C + (size_t)row * EMB + col) =
                make_float2(acc[mt][n][0], acc[mt][n][1]);
            *(float2*)(C + (size_t)(row + 8) * EMB + col) =
                make_float2(acc[mt][n][2], acc[mt][n][3]);
        }
    }
}

// ---------- RoPE + scale + split-convert ----------
__global__ void __launch_bounds__(64) rope_convert(
    const float* __restrict__ q, const float* __restrict__ k,
    __nv_bfloat16* __restrict__ qh, __nv_bfloat16* __restrict__ ql,
    __nv_bfloat16* __restrict__ kh, __nv_bfloat16* __restrict__ kl)
{
    const int s = blockIdx.x;
    const int h = blockIdx.y;
    const int i = threadIdx.x;
    const float SCALE = 0.08838834764831845f;

    const float inv_freq = powf(10000.0f, -(float)i * (1.0f / 64.0f));
    const float ang = (float)s * inv_freq;
    const float c  = cosf(ang);
    const float sn = sinf(ang);

    const size_t base = (size_t)s * EMB + (size_t)h * HD;

    {
        float x0 = q[base + i], x1 = q[base + i + 64];
        float r0 = (x0 * c - x1 * sn) * SCALE;
        float r1 = (x1 * c + x0 * sn) * SCALE;
        __nv_bfloat16 h0, l0, h1, l1;
        split_bf16(r0, h0, l0); split_bf16(r1, h1, l1);
        qh[base + i] = h0;      ql[base + i] = l0;
        qh[base + i + 64] = h1; ql[base + i + 64] = l1;
    }
    {
        float x0 = k[base + i], x1 = k[base + i + 64];
        float r0 = x0 * c - x1 * sn;
        float r1 = x1 * c + x0 * sn;
        __nv_bfloat16 h0, l0, h1, l1;
        split_bf16(r0, h0, l0); split_bf16(r1, h1, l1);
        kh[base + i] = h0;      kl[base + i] = l0;
        kh[base + i + 64] = h1; kl[base + i + 64] = l1;
    }
}

// ---------- V transpose + split ----------
__global__ void __launch_bounds__(256) vtrans(
    const float* __restrict__ v,
    __nv_bfloat16* __restrict__ vth, __nv_bfloat16* __restrict__ vtl)
{
    __shared__ float tile[32][33];
    const int s0 = blockIdx.x * 32;
    const int e0 = blockIdx.y * 32;
    const int tx = threadIdx.x & 31;
    const int ty = threadIdx.x >> 5;

#pragma unroll
    for (int j = 0; j < 4; j++) {
        const int r = ty + j * 8;
        tile[r][tx] = v[(size_t)(s0 + r) * EMB + e0 + tx];
    }
    __syncthreads();
#pragma unroll
    for (int j = 0; j < 4; j++) {
        const int el = ty + j * 8;
        const float x = tile[tx][el];
        __nv_bfloat16 h, l;
        split_bf16(x, h, l);
        const size_t o = (size_t)(e0 + el) * SEQ + s0 + tx;
        vth[o] = h;
        vtl[o] = l;
    }
}

// ---------------- flash attention with HMMA, 512 threads (16 warps) ------------
// CTA: 128 q-rows x 1 head. S warp tile 32x16, PV warp tile 32x32.
#define QSTRIDE 136
#define KSTRIDE 136
#define VSTRIDE 72
#define PSTRIDE 72
#define QHo 0
#define QLo (128 * QSTRIDE)
#define KHo (2 * 128 * QSTRIDE)
#define KLo (KHo + 64 * KSTRIDE)
#define VHo (KHo + 2 * 64 * KSTRIDE)
#define VLo (VHo + 128 * VSTRIDE)
#define PHo (VHo + 2 * 128 * VSTRIDE)
#define PLo (PHo + 128 * PSTRIDE)
#define FB16_TOTAL (PHo + 2 * 128 * PSTRIDE)
#define FRED_OFF   (FB16_TOTAL * 2)                  // bytes
#define FSMEM_BYTES (FRED_OFF + 2 * 4 * 128 * 4)     // pmax/psum [4][128] floats

__global__ void __launch_bounds__(512, 1) flash_mma(
    const __nv_bfloat16* __restrict__ qh, const __nv_bfloat16* __restrict__ ql,
    const __nv_bfloat16* __restrict__ kh, const __nv_bfloat16* __restrict__ kl,
    const __nv_bfloat16* __restrict__ vth, const __nv_bfloat16* __restrict__ vtl,
    float* __restrict__ ctx)
{
    extern __shared__ __align__(16) __nv_bfloat16 fs[];
    float* pmax = (float*)((char*)fs + FRED_OFF);     // [4][128]
    float* psum = pmax + 512;                          // [4][128]

    const int t    = threadIdx.x;
    const int lane = t & 31;
    const int wid  = t >> 5;           // 0..15
    const int wm   = wid & 3;          // 32-row band
    const int wn   = wid >> 2;         // 0..3
    const int id   = lane >> 3;
    const int r8   = lane & 7;
    const int h    = blockIdx.y;
    const int m0   = blockIdx.x * 128;
    const int hb   = h * HD;

    const uint32_t uQH = smem_u32(fs + QHo);
    const uint32_t uQL = smem_u32(fs + QLo);
    const uint32_t uKH = smem_u32(fs + KHo);
    const uint32_t uKL = smem_u32(fs + KLo);
    const uint32_t uVH = smem_u32(fs + VHo);
    const uint32_t uVL = smem_u32(fs + VLo);
    const uint32_t uPH = smem_u32(fs + PHo);
    const uint32_t uPL = smem_u32(fs + PLo);

    // ---- load Q tile once ----
#pragma unroll
    for (int j = 0; j < 4; j++) {
        const int idx = j * 512 + t;
        const int r = idx >> 4;
        const int c = (idx & 15) * 8;
        *(uint4*)(fs + QHo + r * QSTRIDE + c) =
            *(const uint4*)(qh + (size_t)(m0 + r) * EMB + hb + c);
        *(uint4*)(fs + QLo + r * QSTRIDE + c) =
            *(const uint4*)(ql + (size_t)(m0 + r) * EMB + hb + c);
    }

    float acc_o[2][4][4];
#pragma unroll
    for (int i = 0; i < 2; i++)
#pragma unroll
        for (int j = 0; j < 4; j++)
#pragma unroll
            for (int c = 0; c < 4; c++) acc_o[i][j][c] = 0.0f;
    float m_r[2][2], l_r[2][2];
#pragma unroll
    for (int i = 0; i < 2; i++) { m_r[i][0] = m_r[i][1] = -1.0e30f; l_r[i][0] = l_r[i][1] = 0.0f; }

    for (int kb = 0; kb < SEQ / 64; kb++) {
        const int n0 = kb * 64;
        __syncthreads();   // prior PV done with K/V/P smem

        // ---- load K (64x128) and Vt (128x64) ----
#pragma unroll
        for (int j = 0; j < 2; j++) {
            const int idx = j * 512 + t;
            {
                const int r = idx >> 4;
                const int c = (idx & 15) * 8;
                *(uint4*)(fs + KHo + r * KSTRIDE + c) =
                    *(const uint4*)(kh + (size_t)(n0 + r) * EMB + hb + c);
                *(uint4*)(fs + KLo + r * KSTRIDE + c) =
                    *(const uint4*)(kl + (size_t)(n0 + r) * EMB + hb + c);
            }
            {
                const int r = idx >> 3;
                const int c = (idx & 7) * 8;
                *(uint4*)(fs + VHo + r * VSTRIDE + c) =
                    *(const uint4*)(vth + (size_t)(hb + r) * SEQ + n0 + c);
                *(uint4*)(fs + VLo + r * VSTRIDE + c) =
                    *(const uint4*)(vtl + (size_t)(hb + r) * SEQ + n0 + c);
            }
        }
        __syncthreads();

        // ---- S = Q @ K^T (3-term), warp tile 32x16 ----
        float acc_s[2][2][4];
#pragma unroll
        for (int i = 0; i < 2; i++)
#pragma unroll
            for (int j = 0; j < 2; j++)
#pragma unroll
                for (int c = 0; c < 4; c++) acc_s[i][j][c] = 0.0f;

#pragma unroll
        for (int kk = 0; kk < 128; kk += 16) {
            uint32_t ah[2][4], al[2][4];
#pragma unroll
            for (int mt = 0; mt < 2; mt++) {
                const uint32_t offA =
                    ((wm * 32 + mt * 16 + (id & 1) * 8 + r8) * QSTRIDE + kk + (id >> 1) * 8) * 2;
                LDSM4(ah[mt][0], ah[mt][1], ah[mt][2], ah[mt][3], uQH + offA);
                LDSM4(al[mt][0], al[mt][1], al[mt][2], al[mt][3], uQL + offA);
            }
            {
                const uint32_t offB =
                    ((wn * 16 + (id >> 1) * 8 + r8) * KSTRIDE + kk + (id & 1) * 8) * 2;
                uint32_t bh[4], bl[4];
                LDSM4(bh[0], bh[1], bh[2], bh[3], uKH + offB);
                LDSM4(bl[0], bl[1], bl[2], bl[3], uKL + offB);
#pragma unroll
                for (int mt = 0; mt < 2; mt++) {
                    MMA_BF16(acc_s[mt][0], ah[mt], bh[0], bh[1]);
                    MMA_BF16(acc_s[mt][0], ah[mt], bl[0], bl[1]);
                    MMA_BF16(acc_s[mt][0], al[mt], bh[0], bh[1]);
                    MMA_BF16(acc_s[mt][1], ah[mt], bh[2], bh[3]);
                    MMA_BF16(acc_s[mt][1], ah[mt], bl[2], bl[3]);
                    MMA_BF16(acc_s[mt][1], al[mt], bh[2], bh[3]);
                }
            }
        }

        // ---- online softmax (4 wn-warp partials via smem) ----
#pragma unroll
        for (int mt = 0; mt < 2; mt++)
#pragma unroll
            for (int hf = 0; hf < 2; hf++) {
                float mx = fmaxf(fmaxf(acc_s[mt][0][hf * 2], acc_s[mt][0][hf * 2 + 1]),
                                 fmaxf(acc_s[mt][1][hf * 2], acc_s[mt][1][hf * 2 + 1]));
                mx = fmaxf(mx, __shfl_xor_sync(0xffffffffu, mx, 1));
                mx = fmaxf(mx, __shfl_xor_sync(0xffffffffu, mx, 2));
                const int row = wm * 32 + mt * 16 + hf * 8 + (lane >> 2);
                if ((lane & 3) == 0) pmax[wn * 128 + row] = mx;
            }
        __syncthreads();

        float corr_s[2][2];
#pragma unroll
        for (int mt = 0; mt < 2; mt++)
#pragma unroll
            for (int hf = 0; hf < 2; hf++) {
                const int row = wm * 32 + mt * 16 + hf * 8 + (lane >> 2);
                const float mb = fmaxf(fmaxf(pmax[row], pmax[128 + row]),
                                       fmaxf(pmax[256 + row], pmax[384 + row]));
                const float mn = fmaxf(m_r[mt][hf], mb);
                const float corr = __expf(m_r[mt][hf] - mn);
                corr_s[mt][hf] = corr;
                m_r[mt][hf] = mn;
                float ps = 0.0f;
#pragma unroll
                for (int nt = 0; nt < 2; nt++) {
                    float p0 = __expf(acc_s[mt][nt][hf * 2]     - mn);
                    float p1 = __expf(acc_s[mt][nt][hf * 2 + 1] - mn);
                    ps += p0 + p1;
                    __nv_bfloat16 h0, l0, h1, l1;
                    split_bf16(p0, h0, l0); split_bf16(p1, h1, l1);
                    __nv_bfloat162 hp = __halves2bfloat162(h0, h1);
                    __nv_bfloat162 lp = __halves2bfloat162(l0, l1);
                    const int col = wn * 16 + nt * 8 + (lane & 3) * 2;
                    *(uint32_t*)(fs + PHo + row * PSTRIDE + col) = *(uint32_t*)&hp;
                    *(uint32_t*)(fs + PLo + row * PSTRIDE + col) = *(uint32_t*)&lp;
                }
                ps += __shfl_xor_sync(0xffffffffu, ps, 1);
                ps += __shfl_xor_sync(0xffffffffu, ps, 2);
                if ((lane & 3) == 0) psum[wn * 128 + row] = ps;
#pragma unroll
                for (int nt = 0; nt < 4; nt++) {
                    acc_o[mt][nt][hf * 2]     *= corr;
                    acc_o[mt][nt][hf * 2 + 1] *= corr;
                }
            }
        __syncthreads();

#pragma unroll
        for (int mt = 0; mt < 2; mt++)
#pragma unroll
            for (int hf = 0; hf < 2; hf++) {
                const int row = wm * 32 + mt * 16 + hf * 8 + (lane >> 2);
                l_r[mt][hf] = l_r[mt][hf] * corr_s[mt][hf]
                    + psum[row] + psum[128 + row] + psum[256 + row] + psum[384 + row];
            }

        // ---- O += P @ V (3-term), warp tile 32x32 (d) ----
#pragma unroll
        for (int kk = 0; kk < 64; kk += 16) {
            uint32_t pa[2][4], pl[2][4];
#pragma unroll
            for (int mt = 0; mt < 2; mt++) {
                const uint32_t offA =
                    ((wm * 32 + mt * 16 + (id & 1) * 8 + r8) * PSTRIDE + kk + (id >> 1) * 8) * 2;
                LDSM4(pa[mt][0], pa[mt][1], pa[mt][2], pa[mt][3], uPH + offA);
                LDSM4(pl[mt][0], pl[mt][1], pl[mt][2], pl[mt][3], uPL + offA);
            }
#pragma unroll
            for (int nt2 = 0; nt2 < 2; nt2++) {
                const uint32_t offB =
                    ((wn * 32 + nt2 * 16 + (id >> 1) * 8 + r8) * VSTRIDE + kk + (id & 1) * 8) * 2;
                uint32_t bh[4], bl[4];
                LDSM4(bh[0], bh[1], bh[2], bh[3], uVH + offB);
                LDSM4(bl[0], bl[1], bl[2], bl[3], uVL + offB);
#pragma unroll
                for (int mt = 0; mt < 2; mt++) {
                    MMA_BF16(acc_o[mt][nt2 * 2],     pa[mt], bh[0], bh[1]);
                    MMA_BF16(acc_o[mt][nt2 * 2],     pa[mt], bl[0], bl[1]);
                    MMA_BF16(acc_o[mt][nt2 * 2],     pl[mt], bh[0], bh[1]);
                    MMA_BF16(acc_o[mt][nt2 * 2 + 1], pa[mt], bh[2], bh[3]);
                    MMA_BF16(acc_o[mt][nt2 * 2 + 1], pa[mt], bl[2], bl[3]);
                    MMA_BF16(acc_o[mt][nt2 * 2 + 1], pl[mt], bh[2], bh[3]);
                }
            }
        }
    }

    // ---- epilogue ----
#pragma unroll
    for (int mt = 0; mt < 2; mt++)
#pragma unroll
        for (int hf = 0; hf < 2; hf++) {
            const float inv = 1.0f / l_r[mt][hf];
            const int row = m0 + wm * 32 + mt * 16 + hf * 8 + (lane >> 2);
#pragma unroll
            for (int nt = 0; nt < 4; nt++) {
                const int col = hb + wn * 32 + nt * 8 + (lane & 3) * 2;
                *(float2*)(ctx + (size_t)row * EMB + col) =
                    make_float2(acc_o[mt][nt][hf * 2] * inv, acc_o[mt][nt][hf * 2 + 1] * inv);
            }
        }
}

// ---------------- launch ----------------
extern "C" void kernel_launch(void* const* d_in, const int* in_sizes, int n_in,
                              void* d_out, int out_size)
{
    const float* hs = (const float*)d_in[0];
    const float* Wq = (const float*)d_in[1];
    const float* Wk = (const float*)d_in[2];
    const float* Wv = (const float*)d_in[3];
    const float* Wo = (const float*)d_in[4];
    float* out = (float*)d_out;

    float *q, *k, *v, *ctx;
    __nv_bfloat16 *qh, *ql, *kh, *kl, *vth, *vtl;
    cudaGetSymbolAddress((void**)&q,   g_q);
    cudaGetSymbolAddress((void**)&k,   g_k);
    cudaGetSymbolAddress((void**)&v,   g_v);
    cudaGetSymbolAddress((void**)&ctx, g_ctx);
    cudaGetSymbolAddress((void**)&qh,  g_qh);
    cudaGetSymbolAddress((void**)&ql,  g_ql);
    cudaGetSymbolAddress((void**)&kh,  g_kh);
    cudaGetSymbolAddress((void**)&kl,  g_kl);
    cudaGetSymbolAddress((void**)&vth, g_vth);
    cudaGetSymbolAddress((void**)&vtl, g_vtl);

    cudaFuncSetAttribute(gemm_mma,  cudaFuncAttributeMaxDynamicSharedMemorySize, GSM_BYTES);
    cudaFuncSetAttribute(flash_mma, cudaFuncAttributeMaxDynamicSharedMemorySize, FSMEM_BYTES);

    gemm_mma<<<dim3(EMB / 128, SEQ / 128, 3), 512, GSM_BYTES>>>(hs, Wq, Wk, Wv, q, k, v);

    rope_convert<<<dim3(SEQ, NH), 64>>>(q, k, qh, ql, kh, kl);
    vtrans<<<dim3(SEQ / 32, EMB / 32), 256>>>(v, vth, vtl);

    flash_mma<<<dim3(SEQ / 128, NH), 512, FSMEM_BYTES>>>(qh, ql, kh, kl, vth, vtl, ctx);

    gemm_mma<<<dim3(EMB / 128, SEQ / 128, 1), 512, GSM_BYTES>>>(ctx, Wo, Wo, Wo, out, out, out);
}